// round 13
// baseline (speedup 1.0000x reference)
#include <cuda_runtime.h>

#define N_NODES 100000
#define N_EDGES 600000
#define D 128
#define TILE_R 64

// ---------------- device scratch (static, no allocations) ----------------
__device__ __align__(16) float g_h[(size_t)N_NODES * D];  // (1+eps)*x + scatter-sum
__device__ __align__(16) float g_Wt[D * D];               // Wt[k*D+f] = W[f*D+k]
__device__ float g_sum[D];
__device__ float g_sumsq[D];
__device__ float g_scale[D];
__device__ float g_shift[D];
__device__ int   g_is64;                                  // edge_index dtype flag

// ---------------- f32x2 helpers (FFMA2 — ptxas won't emit from C++) ------
__device__ __forceinline__ unsigned long long f2_pack(float2 v) {
    unsigned long long r;
    asm("mov.b64 %0, {%1, %2};" : "=l"(r) : "f"(v.x), "f"(v.y));
    return r;
}
__device__ __forceinline__ void f2_unpack(unsigned long long v, float& a, float& b) {
    asm("mov.b64 {%0, %1}, %2;" : "=f"(a), "=f"(b) : "l"(v));
}
__device__ __forceinline__ unsigned long long f2_fma(unsigned long long a,
                                                     unsigned long long b,
                                                     unsigned long long c) {
    unsigned long long d;
    asm("fma.rn.f32x2 %0, %1, %2, %3;" : "=l"(d) : "l"(a), "l"(b), "l"(c));
    return d;
}

// ---------------- kernel 0: detect int32 vs int64 edge_index -------------
// int64 little-endian values < 2^31 have all-zero high words; int32 random
// indices make 2048 consecutive zeros at odd positions impossible.
__global__ void k_detect(const int* __restrict__ ei32) {
    __shared__ int s[256];
    int t = threadIdx.x;
    int v = 0;
    for (int i = t; i < 2048; i += 256) v |= ei32[2 * i + 1];
    s[t] = v;
    __syncthreads();
    for (int w = 128; w > 0; w >>= 1) {
        if (t < w) s[t] |= s[t + w];
        __syncthreads();
    }
    if (t == 0) g_is64 = (s[0] == 0) ? 1 : 0;
}

// ---------------- kernel 1: h = (1+eps)*x ; zero stat accumulators -------
__global__ void k_init(const float4* __restrict__ x4, const float* __restrict__ eps_p) {
    int i = blockIdx.x * blockDim.x + threadIdx.x;
    float s = 1.0f + *eps_p;
    if (i < N_NODES * (D / 4)) {
        float4 v = x4[i];
        v.x *= s; v.y *= s; v.z *= s; v.w *= s;
        reinterpret_cast<float4*>(g_h)[i] = v;
    }
    if (blockIdx.x == 0 && threadIdx.x < D) {
        g_sum[threadIdx.x] = 0.0f;
        g_sumsq[threadIdx.x] = 0.0f;
    }
}

// ---------------- kernel 2: transpose W into g_Wt -------------------------
__global__ void k_transposeW(const float* __restrict__ W) {
    int i = blockIdx.x * 256 + threadIdx.x;   // 0..16383
    if (i < D * D) {
        int f = i >> 7, k = i & 127;
        g_Wt[k * D + f] = W[i];
    }
}

// ---------------- kernel 3: edge scatter-add (1 warp per edge) -----------
// red.global.add.v4.f32: 16B vector reduction, no return (sm_90+)
__global__ void k_scatter(const float4* __restrict__ x4, const void* __restrict__ ei) {
    int gid = blockIdx.x * blockDim.x + threadIdx.x;
    int e = gid >> 5;
    if (e >= N_EDGES) return;
    int lane = gid & 31;
    int src, dst;
    if (g_is64) {
        const long long* e64 = (const long long*)ei;
        src = (int)e64[e];
        dst = (int)e64[N_EDGES + e];
    } else {
        const int* e32 = (const int*)ei;
        src = e32[e];
        dst = e32[N_EDGES + e];
    }
    if ((unsigned)src >= N_NODES || (unsigned)dst >= N_NODES) return;  // never taken if dtype right
    float4 v = x4[(size_t)src * (D / 4) + lane];
    float* p = g_h + (size_t)dst * D + lane * 4;
    asm volatile("red.global.add.v4.f32 [%0], {%1, %2, %3, %4};"
                 :: "l"(p), "f"(v.x), "f"(v.y), "f"(v.z), "f"(v.w)
                 : "memory");
}

// ---------------- kernel 4: y = h @ W^T + b, fused BN column stats --------
// block: 256 threads = 8 warps. warp ty owns rows [ty*8, ty*8+8), lane tx
// owns features [tx*4, tx*4+4). Wt in smem (64KB), h tile value-duplicated
// in smem (64KB) so LDS.64 returns an f32x2 broadcast pair directly.
__global__ void __launch_bounds__(256, 1) k_gemm(const float* __restrict__ bvec,
                                                 float* __restrict__ y) {
    extern __shared__ float sm[];
    float* Wt_s = sm;             // D*D floats      (16384)
    float* hs2  = sm + D * D;     // TILE_R*D*2 floats (16384)

    int t  = threadIdx.x;
    int tx = t & 31, ty = t >> 5;
    int row0 = blockIdx.x * TILE_R;

    // stage Wt (linear copy, conflict-free)
    {
        float4* d4 = reinterpret_cast<float4*>(Wt_s);
        const float4* s4 = reinterpret_cast<const float4*>(g_Wt);
        #pragma unroll
        for (int i = 0; i < (D * D / 4) / 256; i++) d4[t + i * 256] = s4[t + i * 256];
    }
    // stage h tile, duplicating each value: hs2[(r*D+k)*2 + {0,1}] = h[r][k]
    {
        const float4* gh4 = reinterpret_cast<const float4*>(g_h);
        float4* hs4 = reinterpret_cast<float4*>(hs2);
        #pragma unroll
        for (int it = 0; it < (TILE_R * D / 4) / 256; it++) {
            int i4 = t + it * 256;            // 0..2047
            int r  = i4 >> 5;                 // local row
            int k4 = i4 & 31;                 // float4 chunk within row
            float4 v = make_float4(0.f, 0.f, 0.f, 0.f);
            if (row0 + r < N_NODES) v = gh4[(size_t)(row0 + r) * (D / 4) + k4];
            hs4[r * (D / 2) + k4 * 2 + 0] = make_float4(v.x, v.x, v.y, v.y);
            hs4[r * (D / 2) + k4 * 2 + 1] = make_float4(v.z, v.z, v.w, v.w);
        }
    }
    __syncthreads();

    unsigned long long acc[8][2];
    #pragma unroll
    for (int r = 0; r < 8; r++) { acc[r][0] = 0ull; acc[r][1] = 0ull; }

    #pragma unroll 2
    for (int k = 0; k < D; k++) {
        const float2* wr = reinterpret_cast<const float2*>(Wt_s + k * D);
        unsigned long long wlo = f2_pack(wr[2 * tx]);
        unsigned long long whi = f2_pack(wr[2 * tx + 1]);
        #pragma unroll
        for (int r = 0; r < 8; r++) {
            unsigned long long hk =
                *reinterpret_cast<const unsigned long long*>(hs2 + ((ty * 8 + r) * D + k) * 2);
            acc[r][0] = f2_fma(hk, wlo, acc[r][0]);
            acc[r][1] = f2_fma(hk, whi, acc[r][1]);
        }
    }

    // epilogue: +bias, store, accumulate column sums / sums of squares
    float4 bb = reinterpret_cast<const float4*>(bvec)[tx];
    float s[4]  = {0.f, 0.f, 0.f, 0.f};
    float s2[4] = {0.f, 0.f, 0.f, 0.f};
    #pragma unroll
    for (int r = 0; r < 8; r++) {
        int row = row0 + ty * 8 + r;
        float y0, y1, y2, y3;
        f2_unpack(acc[r][0], y0, y1);
        f2_unpack(acc[r][1], y2, y3);
        y0 += bb.x; y1 += bb.y; y2 += bb.z; y3 += bb.w;
        if (row < N_NODES) {
            reinterpret_cast<float4*>(y + (size_t)row * D)[tx] = make_float4(y0, y1, y2, y3);
            s[0] += y0; s[1] += y1; s[2] += y2; s[3] += y3;
            s2[0] += y0 * y0; s2[1] += y1 * y1; s2[2] += y2 * y2; s2[3] += y3 * y3;
        }
    }

    __syncthreads();                  // done reading hs2; reuse as reduction buffer
    float* red  = hs2;                // [8][D]
    float* red2 = hs2 + 8 * D;        // [8][D]
    #pragma unroll
    for (int j = 0; j < 4; j++) {
        red [ty * D + tx * 4 + j] = s[j];
        red2[ty * D + tx * 4 + j] = s2[j];
    }
    __syncthreads();
    {
        int f = t & 127;
        int which = t >> 7;           // 0 -> sum, 1 -> sumsq
        const float* buf = which ? red2 : red;
        float v = 0.f;
        #pragma unroll
        for (int i = 0; i < 8; i++) v += buf[i * D + f];
        atomicAdd(which ? &g_sumsq[f] : &g_sum[f], v);
    }
}

// ---------------- kernel 5: BN scale/shift (1 block, 128 threads) --------
__global__ void k_finalize(const float* __restrict__ gamma, const float* __restrict__ beta) {
    int f = threadIdx.x;
    const float inv = 1.0f / (float)N_NODES;
    float mean = g_sum[f] * inv;
    float var  = g_sumsq[f] * inv - mean * mean;
    float sc   = gamma[f] * rsqrtf(var + 1e-5f);
    g_scale[f] = sc;
    g_shift[f] = beta[f] - mean * sc;
}

// ---------------- kernel 6: out = relu(y*scale+shift) + x (in-place) -----
__global__ void k_final(const float4* __restrict__ x4, float4* __restrict__ out4) {
    __shared__ float sc[D], sh[D];
    int t = threadIdx.x;
    if (t < D) { sc[t] = g_scale[t]; sh[t] = g_shift[t]; }
    __syncthreads();
    int i = blockIdx.x * 256 + t;
    if (i >= N_NODES * (D / 4)) return;
    int f0 = (i & 31) * 4;
    float4 v  = out4[i];
    float4 xv = x4[i];
    v.x = fmaxf(fmaf(v.x, sc[f0 + 0], sh[f0 + 0]), 0.f) + xv.x;
    v.y = fmaxf(fmaf(v.y, sc[f0 + 1], sh[f0 + 1]), 0.f) + xv.y;
    v.z = fmaxf(fmaf(v.z, sc[f0 + 2], sh[f0 + 2]), 0.f) + xv.z;
    v.w = fmaxf(fmaf(v.w, sc[f0 + 3], sh[f0 + 3]), 0.f) + xv.w;
    out4[i] = v;
}

// ---------------- launch ---------------------------------------------------
extern "C" void kernel_launch(void* const* d_in, const int* in_sizes, int n_in,
                              void* d_out, int out_size) {
    // Map inputs by element count (robust to metadata ordering).
    // Three size-128 vectors keep reference dict order: b, gamma, beta.
    const float* x = nullptr;
    const void*  ei = nullptr;
    const float* W = nullptr;
    const float* eps = nullptr;
    const float* v128[3] = {nullptr, nullptr, nullptr};
    int n128 = 0;
    for (int i = 0; i < n_in; i++) {
        int sz = in_sizes[i];
        if (sz == N_NODES * D)       x   = (const float*)d_in[i];
        else if (sz == 2 * N_EDGES)  ei  = d_in[i];
        else if (sz == D * D)        W   = (const float*)d_in[i];
        else if (sz == 1)            eps = (const float*)d_in[i];
        else if (sz == D && n128 < 3) v128[n128++] = (const float*)d_in[i];
    }
    const float* b     = v128[0];
    const float* gamma = v128[1];
    const float* beta  = v128[2];
    float*       out   = (float*)d_out;

    const float4* x4 = (const float4*)x;

    cudaFuncSetAttribute(k_gemm, cudaFuncAttributeMaxDynamicSharedMemorySize,
                         (D * D + TILE_R * D * 2) * (int)sizeof(float));

    int n_vec4 = N_NODES * (D / 4);                      // 3,200,000
    k_detect<<<1, 256>>>((const int*)ei);
    k_init<<<(n_vec4 + 255) / 256, 256>>>(x4, eps);
    k_transposeW<<<(D * D + 255) / 256, 256>>>(W);
    k_scatter<<<(N_EDGES * 32 + 255) / 256, 256>>>(x4, ei);
    k_gemm<<<(N_NODES + TILE_R - 1) / TILE_R, 256,
             (D * D + TILE_R * D * 2) * (int)sizeof(float)>>>(b, out);
    k_finalize<<<1, D>>>(gamma, beta);
    k_final<<<(n_vec4 + 255) / 256, 256>>>(x4, (float4*)out);
}

// round 14
// speedup vs baseline: 1.0001x; 1.0001x over previous
#include <cuda_runtime.h>

#define N_NODES 100000
#define N_EDGES 600000
#define D 128
#define TILE_R 64

// ---------------- device scratch (static, no allocations) ----------------
__device__ __align__(16) float g_h[(size_t)N_NODES * D];  // (1+eps)*x + scatter-sum
__device__ __align__(16) float g_Wt[D * D];               // Wt[k*D+f] = W[f*D+k]
__device__ float g_sum[D];
__device__ float g_sumsq[D];
__device__ float g_scale[D];
__device__ float g_shift[D];
__device__ int   g_is64;                                  // edge_index dtype flag

// ---------------- f32x2 helpers (FFMA2 — ptxas won't emit from C++) ------
__device__ __forceinline__ unsigned long long f2_pack(float2 v) {
    unsigned long long r;
    asm("mov.b64 %0, {%1, %2};" : "=l"(r) : "f"(v.x), "f"(v.y));
    return r;
}
__device__ __forceinline__ void f2_unpack(unsigned long long v, float& a, float& b) {
    asm("mov.b64 {%0, %1}, %2;" : "=f"(a), "=f"(b) : "l"(v));
}
__device__ __forceinline__ unsigned long long f2_fma(unsigned long long a,
                                                     unsigned long long b,
                                                     unsigned long long c) {
    unsigned long long d;
    asm("fma.rn.f32x2 %0, %1, %2, %3;" : "=l"(d) : "l"(a), "l"(b), "l"(c));
    return d;
}

// ---------------- kernel 0: detect int32 vs int64 edge_index -------------
// int64 little-endian values < 2^31 have all-zero high words; int32 random
// indices make 2048 consecutive zeros at odd positions impossible.
__global__ void k_detect(const int* __restrict__ ei32) {
    __shared__ int s[256];
    int t = threadIdx.x;
    int v = 0;
    for (int i = t; i < 2048; i += 256) v |= ei32[2 * i + 1];
    s[t] = v;
    __syncthreads();
    for (int w = 128; w > 0; w >>= 1) {
        if (t < w) s[t] |= s[t + w];
        __syncthreads();
    }
    if (t == 0) g_is64 = (s[0] == 0) ? 1 : 0;
}

// ---------------- kernel 1: h = (1+eps)*x ; zero stat accumulators -------
__global__ void k_init(const float4* __restrict__ x4, const float* __restrict__ eps_p) {
    int i = blockIdx.x * blockDim.x + threadIdx.x;
    float s = 1.0f + *eps_p;
    if (i < N_NODES * (D / 4)) {
        float4 v = x4[i];
        v.x *= s; v.y *= s; v.z *= s; v.w *= s;
        reinterpret_cast<float4*>(g_h)[i] = v;
    }
    if (blockIdx.x == 0 && threadIdx.x < D) {
        g_sum[threadIdx.x] = 0.0f;
        g_sumsq[threadIdx.x] = 0.0f;
    }
}

// ---------------- kernel 2: transpose W into g_Wt -------------------------
__global__ void k_transposeW(const float* __restrict__ W) {
    int i = blockIdx.x * 256 + threadIdx.x;   // 0..16383
    if (i < D * D) {
        int f = i >> 7, k = i & 127;
        g_Wt[k * D + f] = W[i];
    }
}

// ---------------- kernel 3: edge scatter-add (1 warp per edge) -----------
// red.global.add.v4.f32: 16B vector reduction, no return (sm_90+)
__global__ void k_scatter(const float4* __restrict__ x4, const void* __restrict__ ei) {
    int gid = blockIdx.x * blockDim.x + threadIdx.x;
    int e = gid >> 5;
    if (e >= N_EDGES) return;
    int lane = gid & 31;
    int src, dst;
    if (g_is64) {
        const long long* e64 = (const long long*)ei;
        src = (int)e64[e];
        dst = (int)e64[N_EDGES + e];
    } else {
        const int* e32 = (const int*)ei;
        src = e32[e];
        dst = e32[N_EDGES + e];
    }
    if ((unsigned)src >= N_NODES || (unsigned)dst >= N_NODES) return;  // never taken if dtype right
    float4 v = x4[(size_t)src * (D / 4) + lane];
    float* p = g_h + (size_t)dst * D + lane * 4;
    asm volatile("red.global.add.v4.f32 [%0], {%1, %2, %3, %4};"
                 :: "l"(p), "f"(v.x), "f"(v.y), "f"(v.z), "f"(v.w)
                 : "memory");
}

// ---------------- kernel 4: y = h @ W^T + b, fused BN column stats --------
// block: 256 threads = 8 warps. warp ty owns rows [ty*8, ty*8+8), lane tx
// owns features [tx*4, tx*4+4). Wt in smem (64KB), h tile value-duplicated
// in smem (64KB) so LDS.64 returns an f32x2 broadcast pair directly.
__global__ void __launch_bounds__(256, 1) k_gemm(const float* __restrict__ bvec,
                                                 float* __restrict__ y) {
    extern __shared__ float sm[];
    float* Wt_s = sm;             // D*D floats      (16384)
    float* hs2  = sm + D * D;     // TILE_R*D*2 floats (16384)

    int t  = threadIdx.x;
    int tx = t & 31, ty = t >> 5;
    int row0 = blockIdx.x * TILE_R;

    // stage Wt (linear copy, conflict-free)
    {
        float4* d4 = reinterpret_cast<float4*>(Wt_s);
        const float4* s4 = reinterpret_cast<const float4*>(g_Wt);
        #pragma unroll
        for (int i = 0; i < (D * D / 4) / 256; i++) d4[t + i * 256] = s4[t + i * 256];
    }
    // stage h tile, duplicating each value: hs2[(r*D+k)*2 + {0,1}] = h[r][k]
    {
        const float4* gh4 = reinterpret_cast<const float4*>(g_h);
        float4* hs4 = reinterpret_cast<float4*>(hs2);
        #pragma unroll
        for (int it = 0; it < (TILE_R * D / 4) / 256; it++) {
            int i4 = t + it * 256;            // 0..2047
            int r  = i4 >> 5;                 // local row
            int k4 = i4 & 31;                 // float4 chunk within row
            float4 v = make_float4(0.f, 0.f, 0.f, 0.f);
            if (row0 + r < N_NODES) v = gh4[(size_t)(row0 + r) * (D / 4) + k4];
            hs4[r * (D / 2) + k4 * 2 + 0] = make_float4(v.x, v.x, v.y, v.y);
            hs4[r * (D / 2) + k4 * 2 + 1] = make_float4(v.z, v.z, v.w, v.w);
        }
    }
    __syncthreads();

    unsigned long long acc[8][2];
    #pragma unroll
    for (int r = 0; r < 8; r++) { acc[r][0] = 0ull; acc[r][1] = 0ull; }

    #pragma unroll 2
    for (int k = 0; k < D; k++) {
        const float2* wr = reinterpret_cast<const float2*>(Wt_s + k * D);
        unsigned long long wlo = f2_pack(wr[2 * tx]);
        unsigned long long whi = f2_pack(wr[2 * tx + 1]);
        #pragma unroll
        for (int r = 0; r < 8; r++) {
            unsigned long long hk =
                *reinterpret_cast<const unsigned long long*>(hs2 + ((ty * 8 + r) * D + k) * 2);
            acc[r][0] = f2_fma(hk, wlo, acc[r][0]);
            acc[r][1] = f2_fma(hk, whi, acc[r][1]);
        }
    }

    // epilogue: +bias, store, accumulate column sums / sums of squares
    float4 bb = reinterpret_cast<const float4*>(bvec)[tx];
    float s[4]  = {0.f, 0.f, 0.f, 0.f};
    float s2[4] = {0.f, 0.f, 0.f, 0.f};
    #pragma unroll
    for (int r = 0; r < 8; r++) {
        int row = row0 + ty * 8 + r;
        float y0, y1, y2, y3;
        f2_unpack(acc[r][0], y0, y1);
        f2_unpack(acc[r][1], y2, y3);
        y0 += bb.x; y1 += bb.y; y2 += bb.z; y3 += bb.w;
        if (row < N_NODES) {
            reinterpret_cast<float4*>(y + (size_t)row * D)[tx] = make_float4(y0, y1, y2, y3);
            s[0] += y0; s[1] += y1; s[2] += y2; s[3] += y3;
            s2[0] += y0 * y0; s2[1] += y1 * y1; s2[2] += y2 * y2; s2[3] += y3 * y3;
        }
    }

    __syncthreads();                  // done reading hs2; reuse as reduction buffer
    float* red  = hs2;                // [8][D]
    float* red2 = hs2 + 8 * D;        // [8][D]
    #pragma unroll
    for (int j = 0; j < 4; j++) {
        red [ty * D + tx * 4 + j] = s[j];
        red2[ty * D + tx * 4 + j] = s2[j];
    }
    __syncthreads();
    {
        int f = t & 127;
        int which = t >> 7;           // 0 -> sum, 1 -> sumsq
        const float* buf = which ? red2 : red;
        float v = 0.f;
        #pragma unroll
        for (int i = 0; i < 8; i++) v += buf[i * D + f];
        atomicAdd(which ? &g_sumsq[f] : &g_sum[f], v);
    }
}

// ---------------- kernel 5: BN scale/shift (1 block, 128 threads) --------
__global__ void k_finalize(const float* __restrict__ gamma, const float* __restrict__ beta) {
    int f = threadIdx.x;
    const float inv = 1.0f / (float)N_NODES;
    float mean = g_sum[f] * inv;
    float var  = g_sumsq[f] * inv - mean * mean;
    float sc   = gamma[f] * rsqrtf(var + 1e-5f);
    g_scale[f] = sc;
    g_shift[f] = beta[f] - mean * sc;
}

// ---------------- kernel 6: out = relu(y*scale+shift) + x (in-place) -----
__global__ void k_final(const float4* __restrict__ x4, float4* __restrict__ out4) {
    __shared__ float sc[D], sh[D];
    int t = threadIdx.x;
    if (t < D) { sc[t] = g_scale[t]; sh[t] = g_shift[t]; }
    __syncthreads();
    int i = blockIdx.x * 256 + t;
    if (i >= N_NODES * (D / 4)) return;
    int f0 = (i & 31) * 4;
    float4 v  = out4[i];
    float4 xv = x4[i];
    v.x = fmaxf(fmaf(v.x, sc[f0 + 0], sh[f0 + 0]), 0.f) + xv.x;
    v.y = fmaxf(fmaf(v.y, sc[f0 + 1], sh[f0 + 1]), 0.f) + xv.y;
    v.z = fmaxf(fmaf(v.z, sc[f0 + 2], sh[f0 + 2]), 0.f) + xv.z;
    v.w = fmaxf(fmaf(v.w, sc[f0 + 3], sh[f0 + 3]), 0.f) + xv.w;
    out4[i] = v;
}

// ---------------- launch ---------------------------------------------------
extern "C" void kernel_launch(void* const* d_in, const int* in_sizes, int n_in,
                              void* d_out, int out_size) {
    // Map inputs by element count (robust to metadata ordering).
    // Three size-128 vectors keep reference dict order: b, gamma, beta.
    const float* x = nullptr;
    const void*  ei = nullptr;
    const float* W = nullptr;
    const float* eps = nullptr;
    const float* v128[3] = {nullptr, nullptr, nullptr};
    int n128 = 0;
    for (int i = 0; i < n_in; i++) {
        int sz = in_sizes[i];
        if (sz == N_NODES * D)       x   = (const float*)d_in[i];
        else if (sz == 2 * N_EDGES)  ei  = d_in[i];
        else if (sz == D * D)        W   = (const float*)d_in[i];
        else if (sz == 1)            eps = (const float*)d_in[i];
        else if (sz == D && n128 < 3) v128[n128++] = (const float*)d_in[i];
    }
    const float* b     = v128[0];
    const float* gamma = v128[1];
    const float* beta  = v128[2];
    float*       out   = (float*)d_out;

    const float4* x4 = (const float4*)x;

    cudaFuncSetAttribute(k_gemm, cudaFuncAttributeMaxDynamicSharedMemorySize,
                         (D * D + TILE_R * D * 2) * (int)sizeof(float));

    int n_vec4 = N_NODES * (D / 4);                      // 3,200,000
    k_detect<<<1, 256>>>((const int*)ei);
    k_init<<<(n_vec4 + 255) / 256, 256>>>(x4, eps);
    k_transposeW<<<(D * D + 255) / 256, 256>>>(W);
    k_scatter<<<(N_EDGES * 32 + 255) / 256, 256>>>(x4, ei);
    k_gemm<<<(N_NODES + TILE_R - 1) / TILE_R, 256,
             (D * D + TILE_R * D * 2) * (int)sizeof(float)>>>(b, out);
    k_finalize<<<1, D>>>(gamma, beta);
    k_final<<<(n_vec4 + 255) / 256, 256>>>(x4, (float4*)out);
}

// round 15
// speedup vs baseline: 1.1847x; 1.1846x over previous
#include <cuda_runtime.h>

#define N_NODES 100000
#define N_EDGES 600000
#define D 128
#define TILE_R 64
#define CAP 64          // per-node adjacency bucket capacity (Poisson(6): P(overflow)~1e-40)
#define OVF_CAP 8192

// ---------------- device scratch (static, no allocations) ----------------
__device__ __align__(16) float g_h[(size_t)N_NODES * D];  // (1+eps)*x + agg, then y
__device__ __align__(16) float g_Wt[D * D];               // Wt[k*D+f] = W[f*D+k]
__device__ float g_sum[D];
__device__ float g_sumsq[D];
__device__ float g_scale[D];
__device__ float g_shift[D];
__device__ int   g_is64;                                  // edge_index dtype flag
__device__ int   g_cnt[N_NODES];                          // per-node degree counter
__device__ int   g_adj[(size_t)N_NODES * CAP];            // bucketed adjacency (src ids)
__device__ int   g_ovf_cnt;
__device__ int   g_ovf[OVF_CAP * 2];                      // (src,dst) overflow edges

// ---------------- f32x2 helpers (FFMA2 — ptxas won't emit from C++) ------
__device__ __forceinline__ unsigned long long f2_pack(float2 v) {
    unsigned long long r;
    asm("mov.b64 %0, {%1, %2};" : "=l"(r) : "f"(v.x), "f"(v.y));
    return r;
}
__device__ __forceinline__ void f2_unpack(unsigned long long v, float& a, float& b) {
    asm("mov.b64 {%0, %1}, %2;" : "=f"(a), "=f"(b) : "l"(v));
}
__device__ __forceinline__ unsigned long long f2_fma(unsigned long long a,
                                                     unsigned long long b,
                                                     unsigned long long c) {
    unsigned long long d;
    asm("fma.rn.f32x2 %0, %1, %2, %3;" : "=l"(d) : "l"(a), "l"(b), "l"(c));
    return d;
}

// ---------------- kernel 0: zero counters + detect edge dtype ------------
// int64 LE indices < 2^31 have all-zero odd words; random int32 data cannot
// produce 2048 consecutive zeros at odd positions.
__global__ void k_prep(const int* __restrict__ ei32) {
    int i = blockIdx.x * 256 + threadIdx.x;
    if (i < N_NODES) g_cnt[i] = 0;
    if (i < D) { g_sum[i] = 0.0f; g_sumsq[i] = 0.0f; }
    if (i == 0) g_ovf_cnt = 0;
    if (blockIdx.x == 0) {
        __shared__ int s[256];
        int t = threadIdx.x;
        int v = 0;
        for (int j = t; j < 2048; j += 256) v |= ei32[2 * j + 1];
        s[t] = v;
        __syncthreads();
        for (int w = 128; w > 0; w >>= 1) {
            if (t < w) s[t] |= s[t + w];
            __syncthreads();
        }
        if (t == 0) g_is64 = (s[0] == 0) ? 1 : 0;
    }
}

// ---------------- kernel 1: place edges into per-dst buckets -------------
__global__ void k_place(const void* __restrict__ ei) {
    int e = blockIdx.x * 256 + threadIdx.x;
    if (e >= N_EDGES) return;
    int src, dst;
    if (g_is64) {
        const long long* e64 = (const long long*)ei;
        src = (int)e64[e];
        dst = (int)e64[N_EDGES + e];
    } else {
        const int* e32 = (const int*)ei;
        src = e32[e];
        dst = e32[N_EDGES + e];
    }
    if ((unsigned)src >= N_NODES || (unsigned)dst >= N_NODES) return;
    int pos = atomicAdd(&g_cnt[dst], 1);
    if (pos < CAP) {
        g_adj[(size_t)dst * CAP + pos] = src;
    } else {
        int o = atomicAdd(&g_ovf_cnt, 1);
        if (o < OVF_CAP) { g_ovf[2 * o] = src; g_ovf[2 * o + 1] = dst; }
    }
}

// ---------------- kernel 2: gather-aggregate: h = (1+eps)*x + sum(x[src]) -
// one warp per destination node; lane owns 4 features (float4).
__global__ void k_gather(const float4* __restrict__ x4, const float* __restrict__ eps_p) {
    int gid = blockIdx.x * 256 + threadIdx.x;
    int node = gid >> 5;
    int lane = gid & 31;
    if (node >= N_NODES) return;
    int listed = min(g_cnt[node], CAP);
    const int* lst = g_adj + (size_t)node * CAP;
    // preload index list into two lane registers; broadcast via shfl
    int sA = (lane < listed) ? lst[lane] : 0;
    int sB = (32 + lane < listed) ? lst[32 + lane] : 0;
    float s = 1.0f + *eps_p;
    float4 acc = x4[(size_t)node * (D / 4) + lane];
    acc.x *= s; acc.y *= s; acc.z *= s; acc.w *= s;
    int n1 = min(listed, 32);
    int i = 0;
    for (; i + 1 < n1; i += 2) {   // paired iterations for MLP=2
        int i0 = __shfl_sync(0xffffffffu, sA, i);
        int i1 = __shfl_sync(0xffffffffu, sA, i + 1);
        float4 v0 = x4[(size_t)i0 * (D / 4) + lane];
        float4 v1 = x4[(size_t)i1 * (D / 4) + lane];
        acc.x += v0.x + v1.x; acc.y += v0.y + v1.y;
        acc.z += v0.z + v1.z; acc.w += v0.w + v1.w;
    }
    if (i < n1) {
        int i0 = __shfl_sync(0xffffffffu, sA, i);
        float4 v0 = x4[(size_t)i0 * (D / 4) + lane];
        acc.x += v0.x; acc.y += v0.y; acc.z += v0.z; acc.w += v0.w;
    }
    for (int j = 32; j < listed; j++) {
        int i0 = __shfl_sync(0xffffffffu, sB, j - 32);
        float4 v0 = x4[(size_t)i0 * (D / 4) + lane];
        acc.x += v0.x; acc.y += v0.y; acc.z += v0.z; acc.w += v0.w;
    }
    reinterpret_cast<float4*>(g_h)[(size_t)node * (D / 4) + lane] = acc;
}

// ---------------- kernel 3: overflow edges (expected count 0) ------------
__global__ void k_ovf(const float4* __restrict__ x4) {
    int cnt = min(g_ovf_cnt, OVF_CAP);
    int wid = threadIdx.x >> 5, lane = threadIdx.x & 31;
    for (int e = wid; e < cnt; e += 8) {
        int src = g_ovf[2 * e], dst = g_ovf[2 * e + 1];
        float4 v = x4[(size_t)src * (D / 4) + lane];
        float* p = g_h + (size_t)dst * D + lane * 4;
        asm volatile("red.global.add.v4.f32 [%0], {%1, %2, %3, %4};"
                     :: "l"(p), "f"(v.x), "f"(v.y), "f"(v.z), "f"(v.w)
                     : "memory");
    }
}

// ---------------- kernel 4: transpose W into g_Wt -------------------------
__global__ void k_transposeW(const float* __restrict__ W) {
    int i = blockIdx.x * 256 + threadIdx.x;   // 0..16383
    if (i < D * D) {
        int f = i >> 7, k = i & 127;
        g_Wt[k * D + f] = W[i];
    }
}

// ---------------- kernel 5: y = h @ W^T + b (in-place into g_h), BN stats -
// block: 256 threads = 8 warps. warp ty owns rows [ty*8, ty*8+8), lane tx
// owns features [tx*4, tx*4+4). Wt in smem (64KB), h tile value-duplicated
// in smem (64KB) so LDS.64 returns an f32x2 broadcast pair directly.
__global__ void __launch_bounds__(256, 1) k_gemm(const float* __restrict__ bvec) {
    extern __shared__ float sm[];
    float* Wt_s = sm;             // D*D floats      (16384)
    float* hs2  = sm + D * D;     // TILE_R*D*2 floats (16384)

    int t  = threadIdx.x;
    int tx = t & 31, ty = t >> 5;
    int row0 = blockIdx.x * TILE_R;

    // stage Wt (linear copy, conflict-free)
    {
        float4* d4 = reinterpret_cast<float4*>(Wt_s);
        const float4* s4 = reinterpret_cast<const float4*>(g_Wt);
        #pragma unroll
        for (int i = 0; i < (D * D / 4) / 256; i++) d4[t + i * 256] = s4[t + i * 256];
    }
    // stage h tile, duplicating each value: hs2[(r*D+k)*2 + {0,1}] = h[r][k]
    {
        const float4* gh4 = reinterpret_cast<const float4*>(g_h);
        float4* hs4 = reinterpret_cast<float4*>(hs2);
        #pragma unroll
        for (int it = 0; it < (TILE_R * D / 4) / 256; it++) {
            int i4 = t + it * 256;            // 0..2047
            int r  = i4 >> 5;                 // local row
            int k4 = i4 & 31;                 // float4 chunk within row
            float4 v = make_float4(0.f, 0.f, 0.f, 0.f);
            if (row0 + r < N_NODES) v = gh4[(size_t)(row0 + r) * (D / 4) + k4];
            hs4[r * (D / 2) + k4 * 2 + 0] = make_float4(v.x, v.x, v.y, v.y);
            hs4[r * (D / 2) + k4 * 2 + 1] = make_float4(v.z, v.z, v.w, v.w);
        }
    }
    __syncthreads();

    unsigned long long acc[8][2];
    #pragma unroll
    for (int r = 0; r < 8; r++) { acc[r][0] = 0ull; acc[r][1] = 0ull; }

    #pragma unroll 2
    for (int k = 0; k < D; k++) {
        const float2* wr = reinterpret_cast<const float2*>(Wt_s + k * D);
        unsigned long long wlo = f2_pack(wr[2 * tx]);
        unsigned long long whi = f2_pack(wr[2 * tx + 1]);
        #pragma unroll
        for (int r = 0; r < 8; r++) {
            unsigned long long hk =
                *reinterpret_cast<const unsigned long long*>(hs2 + ((ty * 8 + r) * D + k) * 2);
            acc[r][0] = f2_fma(hk, wlo, acc[r][0]);
            acc[r][1] = f2_fma(hk, whi, acc[r][1]);
        }
    }

    // epilogue: +bias, store back into g_h (stays L2-resident), BN stats
    float4 bb = reinterpret_cast<const float4*>(bvec)[tx];
    float s[4]  = {0.f, 0.f, 0.f, 0.f};
    float s2[4] = {0.f, 0.f, 0.f, 0.f};
    #pragma unroll
    for (int r = 0; r < 8; r++) {
        int row = row0 + ty * 8 + r;
        float y0, y1, y2, y3;
        f2_unpack(acc[r][0], y0, y1);
        f2_unpack(acc[r][1], y2, y3);
        y0 += bb.x; y1 += bb.y; y2 += bb.z; y3 += bb.w;
        if (row < N_NODES) {
            reinterpret_cast<float4*>(g_h + (size_t)row * D)[tx] = make_float4(y0, y1, y2, y3);
            s[0] += y0; s[1] += y1; s[2] += y2; s[3] += y3;
            s2[0] += y0 * y0; s2[1] += y1 * y1; s2[2] += y2 * y2; s2[3] += y3 * y3;
        }
    }

    __syncthreads();                  // done reading hs2; reuse as reduction buffer
    float* red  = hs2;                // [8][D]
    float* red2 = hs2 + 8 * D;        // [8][D]
    #pragma unroll
    for (int j = 0; j < 4; j++) {
        red [ty * D + tx * 4 + j] = s[j];
        red2[ty * D + tx * 4 + j] = s2[j];
    }
    __syncthreads();
    {
        int f = t & 127;
        int which = t >> 7;           // 0 -> sum, 1 -> sumsq
        const float* buf = which ? red2 : red;
        float v = 0.f;
        #pragma unroll
        for (int i = 0; i < 8; i++) v += buf[i * D + f];
        atomicAdd(which ? &g_sumsq[f] : &g_sum[f], v);
    }
}

// ---------------- kernel 6: BN scale/shift (1 block, 128 threads) --------
__global__ void k_finalize(const float* __restrict__ gamma, const float* __restrict__ beta) {
    int f = threadIdx.x;
    const float inv = 1.0f / (float)N_NODES;
    float mean = g_sum[f] * inv;
    float var  = g_sumsq[f] * inv - mean * mean;
    float sc   = gamma[f] * rsqrtf(var + 1e-5f);
    g_scale[f] = sc;
    g_shift[f] = beta[f] - mean * sc;
}

// ---------------- kernel 7: out = relu(y*scale+shift) + x ----------------
__global__ void k_final(const float4* __restrict__ x4, float4* __restrict__ out4) {
    __shared__ float sc[D], sh[D];
    int t = threadIdx.x;
    if (t < D) { sc[t] = g_scale[t]; sh[t] = g_shift[t]; }
    __syncthreads();
    int i = blockIdx.x * 256 + t;
    if (i >= N_NODES * (D / 4)) return;
    int f0 = (i & 31) * 4;
    float4 v  = reinterpret_cast<const float4*>(g_h)[i];
    float4 xv = x4[i];
    v.x = fmaxf(fmaf(v.x, sc[f0 + 0], sh[f0 + 0]), 0.f) + xv.x;
    v.y = fmaxf(fmaf(v.y, sc[f0 + 1], sh[f0 + 1]), 0.f) + xv.y;
    v.z = fmaxf(fmaf(v.z, sc[f0 + 2], sh[f0 + 2]), 0.f) + xv.z;
    v.w = fmaxf(fmaf(v.w, sc[f0 + 3], sh[f0 + 3]), 0.f) + xv.w;
    out4[i] = v;
}

// ---------------- launch ---------------------------------------------------
extern "C" void kernel_launch(void* const* d_in, const int* in_sizes, int n_in,
                              void* d_out, int out_size) {
    // Map inputs by element count (robust to metadata ordering).
    // Three size-128 vectors keep reference dict order: b, gamma, beta.
    const float* x = nullptr;
    const void*  ei = nullptr;
    const float* W = nullptr;
    const float* eps = nullptr;
    const float* v128[3] = {nullptr, nullptr, nullptr};
    int n128 = 0;
    for (int i = 0; i < n_in; i++) {
        int sz = in_sizes[i];
        if (sz == N_NODES * D)       x   = (const float*)d_in[i];
        else if (sz == 2 * N_EDGES)  ei  = d_in[i];
        else if (sz == D * D)        W   = (const float*)d_in[i];
        else if (sz == 1)            eps = (const float*)d_in[i];
        else if (sz == D && n128 < 3) v128[n128++] = (const float*)d_in[i];
    }
    const float* b     = v128[0];
    const float* gamma = v128[1];
    const float* beta  = v128[2];
    float*       out   = (float*)d_out;

    const float4* x4 = (const float4*)x;

    cudaFuncSetAttribute(k_gemm, cudaFuncAttributeMaxDynamicSharedMemorySize,
                         (D * D + TILE_R * D * 2) * (int)sizeof(float));

    int n_vec4 = N_NODES * (D / 4);                      // 3,200,000
    k_prep<<<(N_NODES + 255) / 256, 256>>>((const int*)ei);            // launch 0
    k_place<<<(N_EDGES + 255) / 256, 256>>>(ei);                       // launch 1
    k_gather<<<(N_NODES * 32 + 255) / 256, 256>>>(x4, eps);            // launch 2
    k_ovf<<<1, 256>>>(x4);                                             // launch 3
    k_transposeW<<<(D * D + 255) / 256, 256>>>(W);                     // launch 4
    k_gemm<<<(N_NODES + TILE_R - 1) / TILE_R, 256,                     // launch 5 (ncu -s 5)
             (D * D + TILE_R * D * 2) * (int)sizeof(float)>>>(b);
    k_finalize<<<1, D>>>(gamma, beta);                                 // launch 6
    k_final<<<(n_vec4 + 255) / 256, 256>>>(x4, (float4*)out);          // launch 7
}